// round 2
// baseline (speedup 1.0000x reference)
#include <cuda_runtime.h>

typedef unsigned long long ull;

#define Hh 50      // hidden units
#define Gg 200     // 4*H gates
#define Tt 512     // timesteps
#define Bt 32      // batches per block
#define WS 52      // padded row stride (floats), multiple of 4, pads are zero
#define NT 256     // threads per block
#define NQ 13      // WS/4 float4 chunks per row

// ---- pure register packing + packed fp32x2 FMA (CSE-safe: no memory operands) ----
__device__ __forceinline__ ull pack2(float x, float y) {
    ull r;
    asm("mov.b64 %0, {%1, %2};" : "=l"(r)
        : "r"(__float_as_uint(x)), "r"(__float_as_uint(y)));
    return r;
}
__device__ __forceinline__ ull ffma2(ull a, ull b, ull c) {
    ull d;
    asm("fma.rn.f32x2 %0, %1, %2, %3;" : "=l"(d) : "l"(a), "l"(b), "l"(c));
    return d;
}
__device__ __forceinline__ float f2sum(ull v) {
    unsigned lo, hi;
    asm("mov.b64 {%0, %1}, %2;" : "=r"(lo), "=r"(hi) : "l"(v));
    return __uint_as_float(lo) + __uint_as_float(hi);
}
// ex2-based activations: ~1e-6 error, safe across 512 recurrent steps
__device__ __forceinline__ float sigm(float v) {
    float e = __expf(-v);
    return __fdividef(1.f, 1.f + e);
}
__device__ __forceinline__ float tanh_(float v) {
    float e = __expf(-2.f * v);
    return __fdividef(1.f - e, 1.f + e);
}

// shared layout sizes (floats)
#define SM_W3    (3 * Gg * WS)            // whh0, wih1, whh1 (padded rows)
#define SM_BIAS  (3 * Gg)                 // b0, b1, wih0
#define SM_HC    (4 * Bt * WS)            // h0, c0, h1, c1
#define SM_G     (Gg * Bt)                // gate buffer
#define SM_X     (2 * Bt)                 // double-buffered x
#define SM_FC    (Hh + 4)
#define SM_FLOATS (SM_W3 + SM_BIAS + SM_HC + SM_G + SM_X + SM_FC)
#define SMEM_BYTES (SM_FLOATS * 4)

__global__ __launch_bounds__(NT, 1)
void lstm2_fused_kernel(
    const float* __restrict__ x,      // (B, T, 1)
    const float* __restrict__ wih0,   // (200, 1)
    const float* __restrict__ whh0,   // (200, 50)
    const float* __restrict__ bih0,   // (200)
    const float* __restrict__ bhh0,   // (200)
    const float* __restrict__ wih1,   // (200, 50)
    const float* __restrict__ whh1,   // (200, 50)
    const float* __restrict__ bih1,   // (200)
    const float* __restrict__ bhh1,   // (200)
    const float* __restrict__ fcw,    // (1, 50)
    const float* __restrict__ fcb,    // (1)
    float* __restrict__ out)          // (B, 1)
{
    extern __shared__ float sm[];
    float* s_whh0 = sm;                       // Gg*WS
    float* s_wih1 = s_whh0 + Gg * WS;
    float* s_whh1 = s_wih1 + Gg * WS;
    float* s_b0   = s_whh1 + Gg * WS;         // Gg
    float* s_b1   = s_b0 + Gg;
    float* s_wih0 = s_b1 + Gg;
    float* s_h0   = s_wih0 + Gg;              // Bt*WS each
    float* s_c0   = s_h0 + Bt * WS;
    float* s_h1   = s_c0 + Bt * WS;
    float* s_c1   = s_h1 + Bt * WS;
    float* s_g    = s_c1 + Bt * WS;           // Gg*Bt
    float* s_x    = s_g + Gg * Bt;            // 2*Bt
    float* s_fc   = s_x + 2 * Bt;             // Hh+1

    const int tid  = threadIdx.x;
    const int lane = tid & 31;                // batch within tile
    const int jslot = tid >> 5;               // 0..7, 25 gate rows each
    const int b0   = blockIdx.x * Bt;

    // ---- init: weights (padded rows, pads=0), biases, states ----
    for (int i = tid; i < Gg * WS; i += NT) {
        int j = i / WS, k = i - j * WS;
        float v0 = 0.f, v1 = 0.f, v2 = 0.f;
        if (k < Hh) {
            v0 = whh0[j * Hh + k];
            v1 = wih1[j * Hh + k];
            v2 = whh1[j * Hh + k];
        }
        s_whh0[i] = v0; s_wih1[i] = v1; s_whh1[i] = v2;
    }
    for (int i = tid; i < Gg; i += NT) {
        s_b0[i] = bih0[i] + bhh0[i];
        s_b1[i] = bih1[i] + bhh1[i];
        s_wih0[i] = wih0[i];
    }
    for (int i = tid; i < Bt * WS; i += NT) {
        s_h0[i] = 0.f; s_c0[i] = 0.f; s_h1[i] = 0.f; s_c1[i] = 0.f;
    }
    if (tid < Hh) s_fc[tid] = fcw[tid];
    if (tid == 0) s_fc[Hh] = fcb[0];
    if (tid < Bt) s_x[tid] = x[(ull)(b0 + tid) * Tt];   // t=0 into buf 0
    __syncthreads();

    for (int t = 0; t < Tt; ++t) {
        // prefetch next x a full step ahead (hides DRAM latency)
        float xnext = 0.f;
        if (tid < Bt && t + 1 < Tt) xnext = x[(ull)(b0 + tid) * Tt + (t + 1)];

        const float xv = s_x[(t & 1) * Bt + lane];

        // ---- layer 1 gates: g = b0 + x*wih0 + h0_prev . whh0^T ----
        {
            ull hr[2 * NQ];
            const float4* hp = (const float4*)(s_h0 + lane * WS);
            #pragma unroll
            for (int q = 0; q < NQ; ++q) {
                float4 hv = hp[q];
                hr[2 * q]     = pack2(hv.x, hv.y);
                hr[2 * q + 1] = pack2(hv.z, hv.w);
            }

            for (int m = 0; m < 25; ++m) {
                const int j = jslot * 25 + m;
                const float4* w = (const float4*)(s_whh0 + j * WS);
                ull a0 = 0ULL, a1 = 0ULL;
                #pragma unroll
                for (int q = 0; q < NQ; ++q) {
                    float4 wv = w[q];
                    a0 = ffma2(pack2(wv.x, wv.y), hr[2 * q],     a0);
                    a1 = ffma2(pack2(wv.z, wv.w), hr[2 * q + 1], a1);
                }
                s_g[j * Bt + lane] = s_b0[j] + xv * s_wih0[j] + f2sum(a0) + f2sum(a1);
            }
        }
        __syncthreads();

        // ---- layer 1 cell update ----
        for (int idx = tid; idx < Hh * Bt; idx += NT) {
            int u = idx >> 5, b = idx & 31;
            float gi = sigm (s_g[(u         ) * Bt + b]);
            float gf = sigm (s_g[(u +     Hh) * Bt + b]);
            float gg = tanh_(s_g[(u + 2 * Hh) * Bt + b]);
            float go = sigm (s_g[(u + 3 * Hh) * Bt + b]);
            float c = gf * s_c0[b * WS + u] + gi * gg;
            s_c0[b * WS + u] = c;
            s_h0[b * WS + u] = go * tanh_(c);
        }
        __syncthreads();

        // ---- layer 2 gates: g = b1 + h0_cur . wih1^T + h1_prev . whh1^T ----
        {
            ull h0r[2 * NQ], h1r[2 * NQ];
            const float4* h0p = (const float4*)(s_h0 + lane * WS);
            const float4* h1p = (const float4*)(s_h1 + lane * WS);
            #pragma unroll
            for (int q = 0; q < NQ; ++q) {
                float4 a = h0p[q], b = h1p[q];
                h0r[2 * q]     = pack2(a.x, a.y);
                h0r[2 * q + 1] = pack2(a.z, a.w);
                h1r[2 * q]     = pack2(b.x, b.y);
                h1r[2 * q + 1] = pack2(b.z, b.w);
            }

            for (int m = 0; m < 25; ++m) {
                const int j = jslot * 25 + m;
                const float4* wi = (const float4*)(s_wih1 + j * WS);
                const float4* wh = (const float4*)(s_whh1 + j * WS);
                ull a0 = 0ULL, a1 = 0ULL, a2 = 0ULL, a3 = 0ULL;
                #pragma unroll
                for (int q = 0; q < NQ; ++q) {
                    float4 u = wi[q], v = wh[q];
                    a0 = ffma2(pack2(u.x, u.y), h0r[2 * q],     a0);
                    a1 = ffma2(pack2(u.z, u.w), h0r[2 * q + 1], a1);
                    a2 = ffma2(pack2(v.x, v.y), h1r[2 * q],     a2);
                    a3 = ffma2(pack2(v.z, v.w), h1r[2 * q + 1], a3);
                }
                s_g[j * Bt + lane] = s_b1[j] + (f2sum(a0) + f2sum(a1))
                                             + (f2sum(a2) + f2sum(a3));
            }
        }
        __syncthreads();

        // ---- layer 2 cell update + stage next x ----
        for (int idx = tid; idx < Hh * Bt; idx += NT) {
            int u = idx >> 5, b = idx & 31;
            float gi = sigm (s_g[(u         ) * Bt + b]);
            float gf = sigm (s_g[(u +     Hh) * Bt + b]);
            float gg = tanh_(s_g[(u + 2 * Hh) * Bt + b]);
            float go = sigm (s_g[(u + 3 * Hh) * Bt + b]);
            float c = gf * s_c1[b * WS + u] + gi * gg;
            s_c1[b * WS + u] = c;
            s_h1[b * WS + u] = go * tanh_(c);
        }
        if (tid < Bt) s_x[((t + 1) & 1) * Bt + tid] = xnext;
        __syncthreads();
    }

    // ---- final FC on last h1 ----
    if (tid < Bt) {
        float acc = s_fc[Hh];
        const float* h = s_h1 + tid * WS;
        #pragma unroll
        for (int k = 0; k < Hh; ++k) acc += h[k] * s_fc[k];
        out[b0 + tid] = acc;
    }
}

extern "C" void kernel_launch(void* const* d_in, const int* in_sizes, int n_in,
                              void* d_out, int out_size)
{
    const float* x    = (const float*)d_in[0];
    const float* wih0 = (const float*)d_in[1];
    const float* whh0 = (const float*)d_in[2];
    const float* bih0 = (const float*)d_in[3];
    const float* bhh0 = (const float*)d_in[4];
    const float* wih1 = (const float*)d_in[5];
    const float* whh1 = (const float*)d_in[6];
    const float* bih1 = (const float*)d_in[7];
    const float* bhh1 = (const float*)d_in[8];
    const float* fcw  = (const float*)d_in[9];
    const float* fcb  = (const float*)d_in[10];
    float* out = (float*)d_out;

    const int B = in_sizes[0] / Tt;   // 4096
    const int grid = B / Bt;          // 128 blocks

    cudaFuncSetAttribute(lstm2_fused_kernel,
                         cudaFuncAttributeMaxDynamicSharedMemorySize, SMEM_BYTES);

    lstm2_fused_kernel<<<grid, NT, SMEM_BYTES>>>(
        x, wih0, whh0, bih0, bhh0, wih1, whh1, bih1, bhh1, fcw, fcb, out);
}

// round 3
// speedup vs baseline: 1.0021x; 1.0021x over previous
#include <cuda_runtime.h>

typedef unsigned long long ull;

#define Hh 50      // hidden units
#define Gg 200     // 4*H gates
#define Tt 512     // timesteps
#define Bt 32      // batches per block
#define WS 52      // padded row stride, layer1 weights & c-state (floats)
#define CW 104     // concatenated layer2 row width [wih1(50)+pad2 | whh1(50)+pad2]
#define HS 108     // h01 row stride (27 float4, conflict-free: 12*l mod 32 distinct)
#define NT 512     // threads per block (16 warps)

// ---- pure register packing + packed fp32x2 FMA (CSE-safe: no memory operands) ----
__device__ __forceinline__ ull pack2(float x, float y) {
    ull r;
    asm("mov.b64 %0, {%1, %2};" : "=l"(r)
        : "r"(__float_as_uint(x)), "r"(__float_as_uint(y)));
    return r;
}
__device__ __forceinline__ ull ffma2(ull a, ull b, ull c) {
    ull d;
    asm("fma.rn.f32x2 %0, %1, %2, %3;" : "=l"(d) : "l"(a), "l"(b), "l"(c));
    return d;
}
__device__ __forceinline__ float f2sum(ull v) {
    unsigned lo, hi;
    asm("mov.b64 {%0, %1}, %2;" : "=r"(lo), "=r"(hi) : "l"(v));
    return __uint_as_float(lo) + __uint_as_float(hi);
}
__device__ __forceinline__ float sigm(float v) {
    float e = __expf(-v);
    return __fdividef(1.f, 1.f + e);
}
__device__ __forceinline__ float tanh_(float v) {
    float e = __expf(-2.f * v);
    return __fdividef(1.f - e, 1.f + e);
}

// shared layout (floats)
#define SM_W0    (Gg * WS)     // whh0 padded rows
#define SM_W1    (Gg * CW)     // [wih1|whh1] concatenated padded rows
#define SM_BIAS  (3 * Gg)      // b0, b1, wih0
#define SM_H01   (Bt * HS)     // [h0|h1] per batch
#define SM_C     (2 * Bt * WS) // c0, c1
#define SM_G     (Gg * Bt)
#define SM_X     (2 * Bt)
#define SM_FC    (Hh + 4)
#define SM_FLOATS (SM_W0 + SM_W1 + SM_BIAS + SM_H01 + SM_C + SM_G + SM_X + SM_FC)
#define SMEM_BYTES (SM_FLOATS * 4)

__global__ __launch_bounds__(NT, 1)
void lstm2_fused_kernel(
    const float* __restrict__ x,
    const float* __restrict__ wih0,   // (200,1)
    const float* __restrict__ whh0,   // (200,50)
    const float* __restrict__ bih0,
    const float* __restrict__ bhh0,
    const float* __restrict__ wih1,   // (200,50)
    const float* __restrict__ whh1,   // (200,50)
    const float* __restrict__ bih1,
    const float* __restrict__ bhh1,
    const float* __restrict__ fcw,    // (1,50)
    const float* __restrict__ fcb,    // (1)
    float* __restrict__ out)          // (B,1)
{
    extern __shared__ float sm[];
    float* s_whh0 = sm;                    // Gg*WS
    float* s_w1   = s_whh0 + Gg * WS;      // Gg*CW
    float* s_b0   = s_w1 + Gg * CW;        // Gg
    float* s_b1   = s_b0 + Gg;
    float* s_wih0 = s_b1 + Gg;
    float* s_h01  = s_wih0 + Gg;           // Bt*HS: [0:50)=h0, [52:102)=h1
    float* s_c0   = s_h01 + Bt * HS;       // Bt*WS
    float* s_c1   = s_c0 + Bt * WS;
    float* s_g    = s_c1 + Bt * WS;        // Gg*Bt
    float* s_x    = s_g + Gg * Bt;         // 2*Bt
    float* s_fc   = s_x + 2 * Bt;          // Hh+1

    const int tid  = threadIdx.x;
    const int lane = tid & 31;             // batch within tile
    const int wid  = tid >> 5;             // 0..15
    // rows per warp: warps 0-7 -> 13 rows, warps 8-15 -> 12 rows (8*13+8*12=200)
    const int rbeg = (wid < 8) ? 13 * wid : 104 + 12 * (wid - 8);
    const int rcnt = (wid < 8) ? 13 : 12;
    const int b0   = blockIdx.x * Bt;

    // ---- init: weights (padded, pads=0), biases, states ----
    for (int i = tid; i < Gg * WS; i += NT) {
        int j = i / WS, k = i - j * WS;
        s_whh0[i] = (k < Hh) ? whh0[j * Hh + k] : 0.f;
    }
    for (int i = tid; i < Gg * CW; i += NT) {
        int j = i / CW, k = i - j * CW;
        float v = 0.f;
        if (k < Hh)                    v = wih1[j * Hh + k];
        else if (k >= 52 && k < 52 + Hh) v = whh1[j * Hh + (k - 52)];
        s_w1[i] = v;
    }
    for (int i = tid; i < Gg; i += NT) {
        s_b0[i] = bih0[i] + bhh0[i];
        s_b1[i] = bih1[i] + bhh1[i];
        s_wih0[i] = wih0[i];
    }
    for (int i = tid; i < Bt * HS; i += NT) s_h01[i] = 0.f;
    for (int i = tid; i < 2 * Bt * WS; i += NT) s_c0[i] = 0.f;
    if (tid < Hh) s_fc[tid] = fcw[tid];
    if (tid == 0) s_fc[Hh] = fcb[0];
    if (tid < Bt) s_x[tid] = x[(ull)(b0 + tid) * Tt];
    __syncthreads();

    for (int t = 0; t < Tt; ++t) {
        float xnext = 0.f;
        if (tid < Bt && t + 1 < Tt) xnext = x[(ull)(b0 + tid) * Tt + (t + 1)];

        const float xv = s_x[(t & 1) * Bt + lane];

        // ---- layer 1 gates: g = b0 + x*wih0 + h0_prev . whh0^T ----
        {
            ull hr[26];
            const float4* hp = (const float4*)(s_h01 + lane * HS);  // h0 = first 50
            #pragma unroll
            for (int q = 0; q < 13; ++q) {
                float4 hv = hp[q];
                hr[2 * q]     = pack2(hv.x, hv.y);
                hr[2 * q + 1] = pack2(hv.z, hv.w);
            }
            // note: cols 50,51 of h01 are pads; whh0 pads are 0 so ok only if
            // h pads multiplied by zero weights -> true (w pads zero).
            for (int m = 0; m < rcnt; ++m) {
                const int j = rbeg + m;
                const float4* w = (const float4*)(s_whh0 + j * WS);
                ull a0 = 0ULL, a1 = 0ULL;
                #pragma unroll
                for (int q = 0; q < 13; ++q) {
                    float4 wv = w[q];
                    a0 = ffma2(pack2(wv.x, wv.y), hr[2 * q],     a0);
                    a1 = ffma2(pack2(wv.z, wv.w), hr[2 * q + 1], a1);
                }
                s_g[j * Bt + lane] = s_b0[j] + xv * s_wih0[j] + f2sum(a0) + f2sum(a1);
            }
        }
        __syncthreads();

        // ---- layer 1 cell update: writes h0 into h01[b][0:50] ----
        for (int idx = tid; idx < Hh * Bt; idx += NT) {
            int u = idx >> 5, b = idx & 31;
            float gi = sigm (s_g[(u         ) * Bt + b]);
            float gf = sigm (s_g[(u +     Hh) * Bt + b]);
            float gg = tanh_(s_g[(u + 2 * Hh) * Bt + b]);
            float go = sigm (s_g[(u + 3 * Hh) * Bt + b]);
            float c = gf * s_c0[b * WS + u] + gi * gg;
            s_c0[b * WS + u] = c;
            s_h01[b * HS + u] = go * tanh_(c);
        }
        __syncthreads();

        // ---- layer 2 gates: g = b1 + [h0_cur|h1_prev] . [wih1|whh1]^T ----
        {
            ull hr[26];
            const float4* hp = (const float4*)(s_h01 + lane * HS);  // 104 floats
            #pragma unroll
            for (int q = 0; q < 26; ++q) {
                float4 hv = hp[q];
                hr[q] = pack2(hv.x, hv.y);
                // NOTE: store both halves: use two entries
                // handled below by unrolled pair loads
                (void)hv;
            }
            // redo properly: 26 float4 -> 52 halves is too many regs; instead
            // accumulate inline without persistent h array for second half.
            // Load as pairs directly in the row loop is expensive; so split:
            // we keep 26 ull covering 52 floats at a time (two passes).
            // ---- pass structure below ----
        }
        {
            // two-pass: pass 0 covers floats [0:52) (h0 + pads),
            //           pass 1 covers floats [52:104) (h1 + pads).
            float accv[13];   // partial gate values for this warp's rows
            #pragma unroll
            for (int m = 0; m < 13; ++m) accv[m] = 0.f;

            #pragma unroll
            for (int pass = 0; pass < 2; ++pass) {
                ull hr[26];
                const float4* hp = (const float4*)(s_h01 + lane * HS + pass * 52);
                #pragma unroll
                for (int q = 0; q < 13; ++q) {
                    float4 hv = hp[q];
                    hr[2 * q]     = pack2(hv.x, hv.y);
                    hr[2 * q + 1] = pack2(hv.z, hv.w);
                }
                for (int m = 0; m < rcnt; ++m) {
                    const int j = rbeg + m;
                    const float4* w = (const float4*)(s_w1 + j * CW + pass * 52);
                    ull a0 = 0ULL, a1 = 0ULL;
                    #pragma unroll
                    for (int q = 0; q < 13; ++q) {
                        float4 wv = w[q];
                        a0 = ffma2(pack2(wv.x, wv.y), hr[2 * q],     a0);
                        a1 = ffma2(pack2(wv.z, wv.w), hr[2 * q + 1], a1);
                    }
                    accv[m] += f2sum(a0) + f2sum(a1);
                }
            }
            for (int m = 0; m < rcnt; ++m) {
                const int j = rbeg + m;
                s_g[j * Bt + lane] = s_b1[j] + accv[m];
            }
        }
        __syncthreads();

        // ---- layer 2 cell update: writes h1 into h01[b][52:102] ----
        for (int idx = tid; idx < Hh * Bt; idx += NT) {
            int u = idx >> 5, b = idx & 31;
            float gi = sigm (s_g[(u         ) * Bt + b]);
            float gf = sigm (s_g[(u +     Hh) * Bt + b]);
            float gg = tanh_(s_g[(u + 2 * Hh) * Bt + b]);
            float go = sigm (s_g[(u + 3 * Hh) * Bt + b]);
            float c = gf * s_c1[b * WS + u] + gi * gg;
            s_c1[b * WS + u] = c;
            s_h01[b * HS + 52 + u] = go * tanh_(c);
        }
        if (tid < Bt) s_x[((t + 1) & 1) * Bt + tid] = xnext;
        __syncthreads();
    }

    // ---- final FC on last h1 ----
    if (tid < Bt) {
        float acc = s_fc[Hh];
        const float* h = s_h01 + tid * HS + 52;
        #pragma unroll
        for (int k = 0; k < Hh; ++k) acc += h[k] * s_fc[k];
        out[b0 + tid] = acc;
    }
}

extern "C" void kernel_launch(void* const* d_in, const int* in_sizes, int n_in,
                              void* d_out, int out_size)
{
    const float* x    = (const float*)d_in[0];
    const float* wih0 = (const float*)d_in[1];
    const float* whh0 = (const float*)d_in[2];
    const float* bih0 = (const float*)d_in[3];
    const float* bhh0 = (const float*)d_in[4];
    const float* wih1 = (const float*)d_in[5];
    const float* whh1 = (const float*)d_in[6];
    const float* bih1 = (const float*)d_in[7];
    const float* bhh1 = (const float*)d_in[8];
    const float* fcw  = (const float*)d_in[9];
    const float* fcb  = (const float*)d_in[10];
    float* out = (float*)d_out;

    const int B = in_sizes[0] / Tt;   // 4096
    const int grid = B / Bt;          // 128 blocks

    cudaFuncSetAttribute(lstm2_fused_kernel,
                         cudaFuncAttributeMaxDynamicSharedMemorySize, SMEM_BYTES);

    lstm2_fused_kernel<<<grid, NT, SMEM_BYTES>>>(
        x, wih0, whh0, bih0, bhh0, wih1, whh1, bih1, bhh1, fcw, fcb, out);
}